// round 4
// baseline (speedup 1.0000x reference)
#include <cuda_runtime.h>

// Stacked LSTM wavefront. L=64 layers, T=64 steps, B=16, H=256.
// Anti-diagonal d = t + l; one launch per diagonal.
// (Resubmit #2 after broker timeouts): packed f32x2 FMA mainloop + adaptive
// row-split (RPT) so edge diagonals fill the chip.

#define NL 64
#define NT 64
#define NB 16
#define NH 256
#define KDIM 512   // 2*NH
#define ZDIM 1024  // 4*NH

// Persistent state. g_h double-buffered by diagonal parity.
__device__ float g_c[NL][NB][NH];
__device__ float g_h[2][NL][NB][NH];

__global__ void init_kernel(const float* __restrict__ init_state) {
    int idx = blockIdx.x * blockDim.x + threadIdx.x;
    const int total = NL * NB * NH;
    if (idx >= total) return;
    int l = idx / (NB * NH);
    int r = idx % (NB * NH);
    float c0 = init_state[l * 2 * NB * NH + r];
    float h0 = init_state[l * 2 * NB * NH + NB * NH + r];
    ((float*)g_c)[idx] = c0;
    ((float*)g_h)[idx] = h0;
    ((float*)g_h)[total + idx] = h0;
}

// ── packed fp32x2 helpers ──────────────────────────────────────────────
__device__ __forceinline__ unsigned long long ffma2(unsigned long long a,
                                                    unsigned long long b,
                                                    unsigned long long c) {
    unsigned long long d;
    asm("fma.rn.f32x2 %0, %1, %2, %3;" : "=l"(d) : "l"(a), "l"(b), "l"(c));
    return d;
}
__device__ __forceinline__ unsigned long long packf2(float lo, float hi) {
    unsigned long long r;
    asm("mov.b64 %0, {%1, %2};" : "=l"(r) : "f"(lo), "f"(hi));
    return r;
}
__device__ __forceinline__ float f2sum(unsigned long long v) {
    float a, b;
    asm("mov.b64 {%0, %1}, %2;" : "=f"(a), "=f"(b) : "l"(v));
    return a + b;
}

// ── one diagonal ───────────────────────────────────────────────────────
// RPT = batch rows per thread (16, 4, or 1).
//   G   = 16/RPT row-groups, C = 256/G z-cols per block,
//   HB  = C/4 hidden cols per block, BPC = 256/HB blocks per cell.
// Thread (g, c): z-column j = gate*NH + chunk*HB + hc, rows [g*RPT, g*RPT+RPT).
// K packed in f32x2 pairs; two acc banks (even/odd k-pairs) for ILP.
template <int RPT>
__global__ __launch_bounds__(256)
void diag_kernel(const float* __restrict__ x, const float* __restrict__ W,
                 const float* __restrict__ bias, float* __restrict__ out, int d) {
    constexpr int G   = 16 / RPT;
    constexpr int C   = 256 / G;
    constexpr int HB  = C / 4;
    constexpr int BPC = 256 / HB;

    __shared__ float a_sh[NB][KDIM];  // 32 KB; z-exchange aliases it later

    const int lmin  = (d > (NT - 1)) ? (d - (NT - 1)) : 0;
    const int cell  = blockIdx.x / BPC;
    const int chunk = blockIdx.x % BPC;
    const int l = lmin + cell;
    const int t = d - l;
    const int tid = threadIdx.x;
    const int parity = d & 1;

    const float* __restrict__ hin = &g_h[parity ^ 1][(l == 0) ? 0 : (l - 1)][0][0];
    const float* __restrict__ lh  = &g_h[parity ^ 1][l][0][0];

    // Stage A = [inp | h_rec] as a_sh[b][k], float4-vectorized.
    // 2048 float4s / 256 threads = 8 each; warp-uniform input/recurrent split.
    #pragma unroll
    for (int i = 0; i < 8; i++) {
        int idx = i * 256 + tid;
        int b  = idx >> 7;          // 128 float4 per row
        int k4 = (idx & 127) << 2;  // float index
        float4 v;
        if (k4 < 256) {
            v = (l == 0) ? *(const float4*)&x[((b * NT + t) << 8) + k4]
                         : *(const float4*)&hin[(b << 8) + k4];
        } else {
            v = *(const float4*)&lh[(b << 8) + (k4 - 256)];
        }
        *(float4*)&a_sh[b][k4] = v;
    }
    __syncthreads();

    const int g    = tid / C;
    const int c    = tid % C;
    const int gate = c / HB;
    const int hc   = c % HB;
    const int col  = chunk * HB + hc;
    const int j    = gate * NH + col;
    const int r0   = g * RPT;

    unsigned long long accA[RPT], accB[RPT];
    #pragma unroll
    for (int r = 0; r < RPT; r++) { accA[r] = 0ull; accB[r] = 0ull; }

    const float* __restrict__ wp = W + j;  // W[k][j], row stride ZDIM

    #pragma unroll 2
    for (int k = 0; k < KDIM; k += 4) {
        float w0 = __ldg(wp);
        float w1 = __ldg(wp + ZDIM);
        float w2 = __ldg(wp + 2 * ZDIM);
        float w3 = __ldg(wp + 3 * ZDIM);
        wp += 4 * ZDIM;
        unsigned long long w01 = packf2(w0, w1);
        unsigned long long w23 = packf2(w2, w3);
        #pragma unroll
        for (int r = 0; r < RPT; r++) {
            ulonglong2 av = *(const ulonglong2*)&a_sh[r0 + r][k];  // (a[k],a[k+1]),(a[k+2],a[k+3])
            accA[r] = ffma2(av.x, w01, accA[r]);
            accB[r] = ffma2(av.y, w23, accB[r]);
        }
    }

    // Gate exchange through SMEM (alias a_sh; dead after mainloop).
    __syncthreads();
    float (*z_sh)[HB][NB + 1] = reinterpret_cast<float (*)[HB][NB + 1]>(&a_sh[0][0]);
    {
        float bj = __ldg(&bias[j]);
        #pragma unroll
        for (int r = 0; r < RPT; r++)
            z_sh[gate][hc][r0 + r] = bj + f2sum(accA[r]) + f2sum(accB[r]);
    }
    __syncthreads();

    // Epilogue over (b, hcol) items.
    constexpr int ITEMS = HB * NB;
    constexpr int ITERS = (ITEMS + 255) / 256;
    #pragma unroll
    for (int q = 0; q < ITERS; q++) {
        int it = q * 256 + tid;
        if (ITEMS < 256 && it >= ITEMS) break;
        int b_   = it / HB;
        int hc2  = it % HB;
        int col2 = chunk * HB + hc2;

        float iv = z_sh[0][hc2][b_];
        float jv = z_sh[1][hc2][b_];
        float fv = z_sh[2][hc2][b_];
        float ov = z_sh[3][hc2][b_];

        float lc = g_c[l][b_][col2];
        float sf = 1.0f / (1.0f + expf(-(fv + 1.0f)));
        float si = 1.0f / (1.0f + expf(-iv));
        float so = 1.0f / (1.0f + expf(-ov));
        float nc = sf * lc + si * tanhf(jv);
        float nh = so * tanhf(nc);

        g_c[l][b_][col2] = nc;
        g_h[parity][l][b_][col2] = nh;
        if (l == NL - 1) out[((b_ * NT + t) << 8) + col2] = nh;
    }
}

extern "C" void kernel_launch(void* const* d_in, const int* in_sizes, int n_in,
                              void* d_out, int out_size) {
    const float* x          = (const float*)d_in[0];  // (B,T,H)
    const float* init_state = (const float*)d_in[1];  // (L,2,B,H)
    const float* W          = (const float*)d_in[2];  // (2H,4H)
    const float* bias       = (const float*)d_in[3];  // (4H,)
    float* out              = (float*)d_out;          // (B,T,H)

    {
        int total = NL * NB * NH;
        init_kernel<<<(total + 255) / 256, 256>>>(init_state);
    }

    for (int d = 0; d < NT + NL - 1; d++) {
        int lmin = (d > (NT - 1)) ? (d - (NT - 1)) : 0;
        int lmax = (d < (NL - 1)) ? d : (NL - 1);
        int ncells = lmax - lmin + 1;
        if (ncells >= 24) {
            diag_kernel<16><<<ncells * 4, 256>>>(x, W, bias, out, d);   // blocks >= 96
        } else if (ncells >= 6) {
            diag_kernel<4><<<ncells * 16, 256>>>(x, W, bias, out, d);   // 96..368
        } else {
            diag_kernel<1><<<ncells * 64, 256>>>(x, W, bias, out, d);   // 64..320
        }
    }
}

// round 9
// speedup vs baseline: 1.1932x; 1.1932x over previous
#include <cuda_runtime.h>

// Stacked LSTM wavefront. L=64 layers, T=64 steps, B=16, H=256.
// d = t + l anti-diagonals.
//  - big diagonals: 1 thread per z-col × 16 batch rows, f32x2 FMA (single acc bank)
//  - small diagonals: split-K partial kernel + reduce/epilogue kernel
// (Resubmit after repeated broker timeouts; identical pending design.)

#define NL 64
#define NT 64
#define NB 16
#define NH 256
#define KDIM 512   // 2*NH
#define ZDIM 1024  // 4*NH

__device__ float g_c[NL][NB][NH];
__device__ float g_h[2][NL][NB][NH];         // double-buffered by diagonal parity
__device__ float g_zpart[64][NB][ZDIM];      // split-K partials: 4 MB (max 60 slices used)

__global__ void init_kernel(const float* __restrict__ init_state) {
    int idx = blockIdx.x * blockDim.x + threadIdx.x;
    const int total = NL * NB * NH;
    if (idx >= total) return;
    int l = idx / (NB * NH);
    int r = idx % (NB * NH);
    float c0 = init_state[l * 2 * NB * NH + r];
    float h0 = init_state[l * 2 * NB * NH + NB * NH + r];
    ((float*)g_c)[idx] = c0;
    ((float*)g_h)[idx] = h0;
    ((float*)g_h)[total + idx] = h0;
}

// ── packed fp32x2 helpers ──────────────────────────────────────────────
__device__ __forceinline__ unsigned long long ffma2(unsigned long long a,
                                                    unsigned long long b,
                                                    unsigned long long c) {
    unsigned long long d;
    asm("fma.rn.f32x2 %0, %1, %2, %3;" : "=l"(d) : "l"(a), "l"(b), "l"(c));
    return d;
}
__device__ __forceinline__ unsigned long long packf2(float lo, float hi) {
    unsigned long long r;
    asm("mov.b64 %0, {%1, %2};" : "=l"(r) : "f"(lo), "f"(hi));
    return r;
}
__device__ __forceinline__ float f2sum(unsigned long long v) {
    float a, b;
    asm("mov.b64 {%0, %1}, %2;" : "=f"(a), "=f"(b) : "l"(v));
    return a + b;
}

__device__ __forceinline__ void lstm_epilogue(int l, int b_, int col2, int t, int parity,
                                              float iv, float jv, float fv, float ov,
                                              float* __restrict__ out) {
    float lc = g_c[l][b_][col2];
    float sf = 1.0f / (1.0f + expf(-(fv + 1.0f)));
    float si = 1.0f / (1.0f + expf(-iv));
    float so = 1.0f / (1.0f + expf(-ov));
    float nc = sf * lc + si * tanhf(jv);
    float nh = so * tanhf(nc);
    g_c[l][b_][col2] = nc;
    g_h[parity][l][b_][col2] = nh;
    if (l == NL - 1) out[((b_ * NT + t) << 8) + col2] = nh;
}

// ── big-diagonal kernel: grid = ncells*4, block 256 ───────────────────
// Thread = one z-col (gate*64 cols per chunk), all 16 batch rows.
// Single-bank f32x2 accumulators: 32 regs of acc, no pairing blowup.
__global__ __launch_bounds__(256)
void diag_big(const float* __restrict__ x, const float* __restrict__ W,
              const float* __restrict__ bias, float* __restrict__ out, int d) {
    __shared__ float a_sh[NB][KDIM];  // 32 KB; aliased for z-exchange later

    const int lmin  = (d > (NT - 1)) ? (d - (NT - 1)) : 0;
    const int cell  = blockIdx.x >> 2;
    const int chunk = blockIdx.x & 3;
    const int l = lmin + cell;
    const int t = d - l;
    const int tid = threadIdx.x;
    const int parity = d & 1;

    const float* __restrict__ hin = &g_h[parity ^ 1][(l == 0) ? 0 : (l - 1)][0][0];
    const float* __restrict__ lh  = &g_h[parity ^ 1][l][0][0];

    #pragma unroll
    for (int i = 0; i < 8; i++) {
        int idx = i * 256 + tid;
        int b  = idx >> 7;
        int k4 = (idx & 127) << 2;
        float4 v;
        if (k4 < 256) {
            v = (l == 0) ? *(const float4*)&x[((b * NT + t) << 8) + k4]
                         : *(const float4*)&hin[(b << 8) + k4];
        } else {
            v = *(const float4*)&lh[(b << 8) + (k4 - 256)];
        }
        *(float4*)&a_sh[b][k4] = v;
    }
    __syncthreads();

    const int gate = tid >> 6;
    const int hc   = tid & 63;
    const int col  = chunk * 64 + hc;
    const int j    = gate * NH + col;

    unsigned long long acc2[NB];
    #pragma unroll
    for (int r = 0; r < NB; r++) acc2[r] = 0ull;

    const float* __restrict__ wp = W + j;

    #pragma unroll 2
    for (int k = 0; k < KDIM; k += 4) {
        float w0 = __ldg(wp);
        float w1 = __ldg(wp + ZDIM);
        float w2 = __ldg(wp + 2 * ZDIM);
        float w3 = __ldg(wp + 3 * ZDIM);
        wp += 4 * ZDIM;
        unsigned long long w01 = packf2(w0, w1);
        unsigned long long w23 = packf2(w2, w3);
        #pragma unroll
        for (int r = 0; r < NB; r++) {
            ulonglong2 av = *(const ulonglong2*)&a_sh[r][k];
            acc2[r] = ffma2(av.x, w01, acc2[r]);
            acc2[r] = ffma2(av.y, w23, acc2[r]);
        }
    }

    __syncthreads();
    float (*z_sh)[64][NB + 1] = reinterpret_cast<float (*)[64][NB + 1]>(&a_sh[0][0]);
    {
        float bj = __ldg(&bias[j]);
        #pragma unroll
        for (int r = 0; r < NB; r++)
            z_sh[gate][hc][r] = bj + f2sum(acc2[r]);
    }
    __syncthreads();

    const int hc2 = tid & 63;
    const int bg  = tid >> 6;
    const int col2 = chunk * 64 + hc2;
    #pragma unroll
    for (int q = 0; q < 4; q++) {
        int b_ = bg * 4 + q;
        lstm_epilogue(l, b_, col2, t, parity,
                      z_sh[0][hc2][b_], z_sh[1][hc2][b_],
                      z_sh[2][hc2][b_], z_sh[3][hc2][b_], out);
    }
}

// ── small-diagonal split-K partial kernel ─────────────────────────────
// grid = ncells*4*KSPLIT, block 256. Thread = one z-col, 16 rows, K-slice KSLEN.
// Writes raw partials to g_zpart[cell*KSPLIT+ks].
template <int KSLEN>
__global__ __launch_bounds__(256)
void diag_partial(const float* __restrict__ x, const float* __restrict__ W,
                  float* __restrict__ out_unused, int d) {
    constexpr int KSPLIT = KDIM / KSLEN;
    __shared__ float a_sh[NB][KSLEN];

    const int lmin  = (d > (NT - 1)) ? (d - (NT - 1)) : 0;
    const int cell  = blockIdx.x / (4 * KSPLIT);
    const int chunk = (blockIdx.x / KSPLIT) & 3;
    const int ks    = blockIdx.x % KSPLIT;
    const int l = lmin + cell;
    const int t = d - l;
    const int tid = threadIdx.x;
    const int parity = d & 1;
    const int k0 = ks * KSLEN;

    const float* __restrict__ hin = &g_h[parity ^ 1][(l == 0) ? 0 : (l - 1)][0][0];
    const float* __restrict__ lh  = &g_h[parity ^ 1][l][0][0];

    // Stage the A k-slice. k0 aligned to KSLEN; KSLEN<=256 -> slice wholly in
    // input half or recurrent half (uniform branch).
    {
        constexpr int NF4 = NB * KSLEN / 4;
        for (int i = tid; i < NF4; i += 256) {
            int b   = i / (KSLEN / 4);
            int kk4 = (i % (KSLEN / 4)) << 2;
            int kg  = k0 + kk4;
            float4 v;
            if (kg < 256) {
                v = (l == 0) ? *(const float4*)&x[((b * NT + t) << 8) + kg]
                             : *(const float4*)&hin[(b << 8) + kg];
            } else {
                v = *(const float4*)&lh[(b << 8) + (kg - 256)];
            }
            *(float4*)&a_sh[b][kk4] = v;
        }
    }
    __syncthreads();

    const int gate = tid >> 6;
    const int hc   = tid & 63;
    const int col  = chunk * 64 + hc;
    const int j    = gate * NH + col;

    unsigned long long acc2[NB];
    #pragma unroll
    for (int r = 0; r < NB; r++) acc2[r] = 0ull;

    const float* __restrict__ wp = W + (size_t)k0 * ZDIM + j;

    #pragma unroll 2
    for (int kk = 0; kk < KSLEN; kk += 4) {
        float w0 = __ldg(wp);
        float w1 = __ldg(wp + ZDIM);
        float w2 = __ldg(wp + 2 * ZDIM);
        float w3 = __ldg(wp + 3 * ZDIM);
        wp += 4 * ZDIM;
        unsigned long long w01 = packf2(w0, w1);
        unsigned long long w23 = packf2(w2, w3);
        #pragma unroll
        for (int r = 0; r < NB; r++) {
            ulonglong2 av = *(const ulonglong2*)&a_sh[r][kk];
            acc2[r] = ffma2(av.x, w01, acc2[r]);
            acc2[r] = ffma2(av.y, w23, acc2[r]);
        }
    }

    const int slice = cell * KSPLIT + ks;
    #pragma unroll
    for (int r = 0; r < NB; r++)
        g_zpart[slice][r][j] = f2sum(acc2[r]);  // lanes: consecutive j -> coalesced
}

// ── small-diagonal reduce + epilogue ──────────────────────────────────
// grid = ncells*4, block 256. Thread handles 4 (b, hc) items.
__global__ __launch_bounds__(256)
void diag_reduce(const float* __restrict__ bias, float* __restrict__ out,
                 int d, int kplit) {
    const int lmin  = (d > (NT - 1)) ? (d - (NT - 1)) : 0;
    const int cell  = blockIdx.x >> 2;
    const int chunk = blockIdx.x & 3;
    const int l = lmin + cell;
    const int t = d - l;
    const int tid = threadIdx.x;
    const int parity = d & 1;
    const int base_slice = cell * kplit;

    #pragma unroll
    for (int q = 0; q < 4; q++) {
        int it  = q * 256 + tid;
        int b_  = it >> 6;
        int hc  = it & 63;
        int col = chunk * 64 + hc;

        float s[4];
        #pragma unroll
        for (int g4 = 0; g4 < 4; g4++) {
            int j = g4 * NH + col;
            float acc = __ldg(&bias[j]);
            for (int ksi = 0; ksi < kplit; ksi++)
                acc += g_zpart[base_slice + ksi][b_][j];
            s[g4] = acc;
        }
        lstm_epilogue(l, b_, col, t, parity, s[0], s[1], s[2], s[3], out);
    }
}

extern "C" void kernel_launch(void* const* d_in, const int* in_sizes, int n_in,
                              void* d_out, int out_size) {
    const float* x          = (const float*)d_in[0];  // (B,T,H)
    const float* init_state = (const float*)d_in[1];  // (L,2,B,H)
    const float* W          = (const float*)d_in[2];  // (2H,4H)
    const float* bias       = (const float*)d_in[3];  // (4H,)
    float* out              = (float*)d_out;          // (B,T,H)

    {
        int total = NL * NB * NH;
        init_kernel<<<(total + 255) / 256, 256>>>(init_state);
    }

    for (int d = 0; d < NT + NL - 1; d++) {
        int lmin = (d > (NT - 1)) ? (d - (NT - 1)) : 0;
        int lmax = (d < (NL - 1)) ? d : (NL - 1);
        int ncells = lmax - lmin + 1;

        if (ncells >= 24) {
            diag_big<<<ncells * 4, 256>>>(x, W, bias, out, d);
        } else {
            int kplit = (ncells <= 3) ? 16 : (ncells <= 7) ? 8 : (ncells <= 15) ? 4 : 2;
            int grid = ncells * 4 * kplit;
            switch (kplit) {
                case 16: diag_partial<32 ><<<grid, 256>>>(x, W, out, d); break;
                case 8:  diag_partial<64 ><<<grid, 256>>>(x, W, out, d); break;
                case 4:  diag_partial<128><<<grid, 256>>>(x, W, out, d); break;
                default: diag_partial<256><<<grid, 256>>>(x, W, out, d); break;
            }
            diag_reduce<<<ncells * 4, 256>>>(bias, out, d, kplit);
        }
    }
}